// round 13
// baseline (speedup 1.0000x reference)
#include <cuda_runtime.h>
#include <cuda_fp16.h>
#include <cstdint>

#define NN 500000
#define FF 128
#define HH 256
#define CC 40
#define IPB 2048                       // items per scan block (256 thr x 8)
#define NBLK ((NN + IPB - 1) / IPB)    // 245

static_assert(NBLK <= 256, "scan2 single block");

// ---- scratch (device globals; no allocations allowed) ----
__device__ int g_first_pos[NN];
__device__ int g_excl[NN];        // reused: scan1 excl, then partition excl
__device__ int g_bsum[NBLK];
__device__ int g_bsumx[NBLK];
__device__ int g_mapped[NN];
__device__ int g_U;
__device__ int g_TA;              // rows in partition A (target < U/2)
__device__ int g_list[NN];        // row indices: [0,TA) -> A, [TA,NN) -> B
__device__ __align__(128) __half g_aggh[(size_t)NN * HH];   // 256 MB fp16

// pre-converted fp16 W images, transposed to [n][k] with ldmatrix pitch
// pitch1 = 272 B (272 % 128 == 16 -> conflict-free ldmatrix)
// pitch2 = 528 B (528 % 128 == 16)
__device__ __align__(16) unsigned char g_B1h[256 * 272];
__device__ __align__(16) unsigned char g_B2h[40 * 528];

// ---------------- helpers ----------------

__device__ __forceinline__ uint32_t smem_u32(const void* p) {
    uint32_t a;
    asm("{ .reg .u64 t; cvta.to.shared.u64 t, %1; cvt.u32.u64 %0, t; }"
        : "=r"(a) : "l"(p));
    return a;
}

__device__ __forceinline__ uint32_t f2h2u(float a, float b) {
    __half2 h = __floats2half2_rn(a, b);
    return *reinterpret_cast<uint32_t*>(&h);
}

#define LDSM4(r, addr)                                                         \
    asm volatile("ldmatrix.sync.aligned.m8n8.x4.shared.b16 {%0,%1,%2,%3},[%4];"\
                 : "=r"((r)[0]), "=r"((r)[1]), "=r"((r)[2]), "=r"((r)[3])      \
                 : "r"(addr))
#define LDSM2(r, addr)                                                         \
    asm volatile("ldmatrix.sync.aligned.m8n8.x2.shared.b16 {%0,%1},[%2];"      \
                 : "=r"((r)[0]), "=r"((r)[1]) : "r"(addr))
#define MMA16816(d, a, b)                                                      \
    asm volatile(                                                              \
        "mma.sync.aligned.m16n8k16.row.col.f32.f16.f16.f32 "                   \
        "{%0,%1,%2,%3},{%4,%5,%6,%7},{%8,%9},{%0,%1,%2,%3};"                   \
        : "+f"((d)[0]), "+f"((d)[1]), "+f"((d)[2]), "+f"((d)[3])               \
        : "r"((a)[0]), "r"((a)[1]), "r"((a)[2]), "r"((a)[3]),                  \
          "r"((b)[0]), "r"((b)[1]))

// ---------------- mapping pipeline (unchanged, verified) ----------------

__global__ void k_init_firstpos() {
    int i = blockIdx.x * blockDim.x + threadIdx.x;
    if (i < NN) g_first_pos[i] = NN;
}

__global__ void k_firstpos(const int* __restrict__ ei) {
    int i = blockIdx.x * blockDim.x + threadIdx.x;
    if (i < NN) atomicMin(&g_first_pos[ei[2 * i]], i);
}

__global__ __launch_bounds__(256) void k_scan1(const int* __restrict__ ei) {
    int t = threadIdx.x, b = blockIdx.x;
    int base = b * IPB + t * 8;
    int f[8]; int ls = 0;
#pragma unroll
    for (int j = 0; j < 8; j++) {
        int i = base + j;
        int v = 0;
        if (i < NN) { int s = ei[2 * i]; v = (g_first_pos[s] == i) ? 1 : 0; }
        f[j] = v; ls += v;
    }
    int lane = t & 31, wid = t >> 5;
    int incl = ls;
#pragma unroll
    for (int o = 1; o < 32; o <<= 1) {
        int n = __shfl_up_sync(0xffffffffu, incl, o);
        if (lane >= o) incl += n;
    }
    __shared__ int wtot[8], woff[8];
    if (lane == 31) wtot[wid] = incl;
    __syncthreads();
    if (t < 8) {
        int s = 0;
        for (int j = 0; j < t; j++) s += wtot[j];
        woff[t] = s;
    }
    __syncthreads();
    int run = woff[wid] + (incl - ls);
#pragma unroll
    for (int j = 0; j < 8; j++) {
        int i = base + j;
        if (i < NN) g_excl[i] = run;
        run += f[j];
    }
    if (t == 255) g_bsum[b] = run;
}

__global__ __launch_bounds__(256) void k_scan2() {
    int t = threadIdx.x;
    int v = (t < NBLK) ? g_bsum[t] : 0;
    int lane = t & 31, wid = t >> 5;
    int incl = v;
#pragma unroll
    for (int o = 1; o < 32; o <<= 1) {
        int n = __shfl_up_sync(0xffffffffu, incl, o);
        if (lane >= o) incl += n;
    }
    __shared__ int wtot[8], woff[8];
    if (lane == 31) wtot[wid] = incl;
    __syncthreads();
    if (t < 8) {
        int s = 0;
        for (int j = 0; j < t; j++) s += wtot[j];
        woff[t] = s;
    }
    __syncthreads();
    int excl = woff[wid] + incl - v;
    if (t < NBLK) g_bsumx[t] = excl;
    if (t == 255) g_U = excl + v;
}

__global__ void k_mapped(const int* __restrict__ ei) {
    int i = blockIdx.x * blockDim.x + threadIdx.x;
    if (i < NN) {
        int j  = ei[2 * i];
        int s2 = ei[2 * j];
        int p  = g_first_pos[s2];
        g_mapped[i] = g_excl[p] + g_bsumx[p / IPB];
    }
}

// ---- partition rows by target half: flag = (mapped[i] < U/2) ----
// reuses g_excl / g_bsum / g_bsumx (dead after k_mapped)

__global__ __launch_bounds__(256) void k_scanA1() {
    int Uh = g_U >> 1;
    int t = threadIdx.x, b = blockIdx.x;
    int base = b * IPB + t * 8;
    int f[8]; int ls = 0;
#pragma unroll
    for (int j = 0; j < 8; j++) {
        int i = base + j;
        int v = (i < NN) ? (g_mapped[i] < Uh ? 1 : 0) : 0;
        f[j] = v; ls += v;
    }
    int lane = t & 31, wid = t >> 5;
    int incl = ls;
#pragma unroll
    for (int o = 1; o < 32; o <<= 1) {
        int n = __shfl_up_sync(0xffffffffu, incl, o);
        if (lane >= o) incl += n;
    }
    __shared__ int wtot[8], woff[8];
    if (lane == 31) wtot[wid] = incl;
    __syncthreads();
    if (t < 8) {
        int s = 0;
        for (int j = 0; j < t; j++) s += wtot[j];
        woff[t] = s;
    }
    __syncthreads();
    int run = woff[wid] + (incl - ls);
#pragma unroll
    for (int j = 0; j < 8; j++) {
        int i = base + j;
        if (i < NN) g_excl[i] = run;
        run += f[j];
    }
    if (t == 255) g_bsum[b] = run;
}

__global__ __launch_bounds__(256) void k_scanA2() {
    int t = threadIdx.x;
    int v = (t < NBLK) ? g_bsum[t] : 0;
    int lane = t & 31, wid = t >> 5;
    int incl = v;
#pragma unroll
    for (int o = 1; o < 32; o <<= 1) {
        int n = __shfl_up_sync(0xffffffffu, incl, o);
        if (lane >= o) incl += n;
    }
    __shared__ int wtot[8], woff[8];
    if (lane == 31) wtot[wid] = incl;
    __syncthreads();
    if (t < 8) {
        int s = 0;
        for (int j = 0; j < t; j++) s += wtot[j];
        woff[t] = s;
    }
    __syncthreads();
    int excl = woff[wid] + incl - v;
    if (t < NBLK) g_bsumx[t] = excl;
    if (t == 255) g_TA = excl + v;
}

__global__ void k_fill() {
    int i = blockIdx.x * blockDim.x + threadIdx.x;
    if (i >= NN) return;
    int Uh = g_U >> 1;
    int posA = g_excl[i] + g_bsumx[i / IPB];
    if (g_mapped[i] < Uh) g_list[posA] = i;
    else                  g_list[g_TA + i - posA] = i;
}

// zero agg target-row range for pass p: [0,U/2) or [U/2,U)
__global__ void k_zero_rows(int p) {
    int U = g_U, Uh = U >> 1;
    int r0 = p ? Uh : 0, r1 = p ? U : Uh;
    size_t total = (size_t)(r1 - r0) * 32;   // 32 uint4 per 256-col fp16 row
    uint4* base = (uint4*)g_aggh + (size_t)r0 * 32;
    uint4 z = make_uint4(0, 0, 0, 0);
    for (size_t i = blockIdx.x * (size_t)blockDim.x + threadIdx.x; i < total;
         i += (size_t)gridDim.x * blockDim.x)
        base[i] = z;
}

// ---------------- weight prep: transpose + fp16, padded pitch ----------------

__global__ void k_prep1(const float* __restrict__ W1) {
    int idx = blockIdx.x * blockDim.x + threadIdx.x;   // 256*128
    if (idx >= HH * FF) return;
    int n = idx >> 7, k = idx & 127;
    float v = W1[(size_t)k * HH + n];
    uint32_t off = (uint32_t)n * 272 + (uint32_t)k * 2;
    *(unsigned short*)(g_B1h + off) = __half_as_ushort(__float2half_rn(v));
}

__global__ void k_prep2(const float* __restrict__ W2) {
    int idx = blockIdx.x * blockDim.x + threadIdx.x;   // 40*256
    if (idx >= CC * HH) return;
    int n = idx >> 8, k = idx & 255;
    float v = W2[(size_t)k * CC + n];
    uint32_t off = (uint32_t)n * 528 + (uint32_t)k * 2;
    *(unsigned short*)(g_B2h + off) = __half_as_ushort(__float2half_rn(v));
}

// ---------------- GEMM1 (HMMA fp16): relu(x@W1+b1) fused scatter ----------------
// CTA: M=128 list rows, N=256 (full H), K=128. 512 threads, 4x4 warps.
// pass p processes g_list[off .. off+count); atomics confined to one U-half.
#define G1_SMEM 104448   // A(34816)+B(69632); Cs(67584) reuses it per half

__global__ __launch_bounds__(512, 1)
void k_g1(const float* __restrict__ x, const float* __restrict__ b1, int p) {
    extern __shared__ __align__(16) char sm[];
    __shared__ float sb1[256];
    __shared__ int srow[128];
    uint32_t sA = smem_u32(sm);
    uint32_t sB = sA + 34816;

    int tid = threadIdx.x, lane = tid & 31, wid = tid >> 5;
    int TA = g_TA;
    int off = p ? TA : 0;
    int count = p ? (NN - TA) : TA;
    int rowBase = blockIdx.x * 128;
    if (rowBase >= count) return;

    if (tid < 256) sb1[tid] = b1[tid];
    if (tid < 128) {
        int idx = rowBase + tid;
        srow[tid] = (idx < count) ? g_list[off + idx] : -1;
    }
    __syncthreads();

    // copy full pre-converted B image (256 rows, pitch 272B) = 4352 uint4
    {
        const uint4* srcH = (const uint4*)g_B1h;
        uint4* dH = (uint4*)(sm + 34816);
#pragma unroll
        for (int i = tid; i < 4352; i += 512) dH[i] = srcH[i];
    }
    // stage A: gather x rows via list, convert fp16, pitch 272B
#pragma unroll
    for (int q = tid; q < 2048; q += 512) {
        int m = q >> 4, g = q & 15;
        int row = srow[m];
        float a[8];
        if (row >= 0) {
            float4 v0 = __ldcs((const float4*)&x[(size_t)row * FF + g * 8]);
            float4 v1 = __ldcs((const float4*)&x[(size_t)row * FF + g * 8 + 4]);
            a[0] = v0.x; a[1] = v0.y; a[2] = v0.z; a[3] = v0.w;
            a[4] = v1.x; a[5] = v1.y; a[6] = v1.z; a[7] = v1.w;
        } else {
#pragma unroll
            for (int j = 0; j < 8; j++) a[j] = 0.f;
        }
        uint4 ph;
        ph.x = f2h2u(a[0], a[1]);
        ph.y = f2h2u(a[2], a[3]);
        ph.z = f2h2u(a[4], a[5]);
        ph.w = f2h2u(a[6], a[7]);
        *(uint4*)(sm + m * 272 + g * 16) = ph;
    }
    __syncthreads();

    int mRow = (wid & 3) * 32, nCol = (wid >> 2) * 64;   // nCol in {0,64,128,192}
    float acc[2][8][4];
#pragma unroll
    for (int i = 0; i < 2; i++)
#pragma unroll
        for (int j = 0; j < 8; j++)
#pragma unroll
            for (int e = 0; e < 4; e++) acc[i][j][e] = 0.f;

#pragma unroll
    for (int ks = 0; ks < 8; ks++) {
        uint32_t af[2][4];
#pragma unroll
        for (int mt = 0; mt < 2; mt++) {
            uint32_t ad = sA + (mRow + mt * 16 + (lane & 15)) * 272 +
                          (ks * 16 + (lane >> 4) * 8) * 2;
            LDSM4(af[mt], ad);
        }
        uint32_t bf[8][2];
#pragma unroll
        for (int pq = 0; pq < 4; pq++) {
            uint32_t r4[4];
            uint32_t bd = sB +
                (nCol + pq * 16 + ((lane >> 4) & 1) * 8 + (lane & 7)) * 272 +
                (ks * 16 + ((lane >> 3) & 1) * 8) * 2;
            LDSM4(r4, bd);
            bf[2 * pq][0] = r4[0]; bf[2 * pq][1] = r4[1];
            bf[2 * pq + 1][0] = r4[2]; bf[2 * pq + 1][1] = r4[3];
        }
#pragma unroll
        for (int mt = 0; mt < 2; mt++)
#pragma unroll
            for (int nt = 0; nt < 8; nt++)
                MMA16816(acc[mt][nt], af[mt], bf[nt]);
    }

    // epilogue in two column halves through smem Cs (128 rows x pitch 132 f32)
    float* Cs = (float*)sm;
    int row = tid & 127, cq = tid >> 7;          // 4 threads per row, 32 cols ea
    int grow = srow[row];
    int tgt = (grow >= 0) ? g_mapped[grow] : 0;

#pragma unroll
    for (int h = 0; h < 2; h++) {
        __syncthreads();   // protect A/B (h=0) or previous Cs reads (h=1)
        if ((nCol >> 7) == h) {
            int nColL = nCol & 127;
#pragma unroll
            for (int mt = 0; mt < 2; mt++)
#pragma unroll
                for (int nt = 0; nt < 8; nt++) {
                    int r = mRow + mt * 16 + (lane >> 2);
                    int cc = nColL + nt * 8 + (lane & 3) * 2;
                    *(float2*)&Cs[r * 132 + cc] =
                        make_float2(acc[mt][nt][0], acc[mt][nt][1]);
                    *(float2*)&Cs[(r + 8) * 132 + cc] =
                        make_float2(acc[mt][nt][2], acc[mt][nt][3]);
                }
        }
        __syncthreads();

        if (grow >= 0) {
            __half* dst = g_aggh + (size_t)tgt * HH + h * 128 + cq * 32;
            const float* csrc = Cs + row * 132 + cq * 32;
#pragma unroll
            for (int q = 0; q < 4; q++) {
                float4 va = *(const float4*)&csrc[q * 8];
                float4 vb = *(const float4*)&csrc[q * 8 + 4];
                int cb = h * 128 + cq * 32 + q * 8;
                uint32_t p0 = f2h2u(fmaxf(va.x + sb1[cb], 0.f),
                                    fmaxf(va.y + sb1[cb + 1], 0.f));
                uint32_t p1 = f2h2u(fmaxf(va.z + sb1[cb + 2], 0.f),
                                    fmaxf(va.w + sb1[cb + 3], 0.f));
                uint32_t p2 = f2h2u(fmaxf(vb.x + sb1[cb + 4], 0.f),
                                    fmaxf(vb.y + sb1[cb + 5], 0.f));
                uint32_t p3 = f2h2u(fmaxf(vb.z + sb1[cb + 6], 0.f),
                                    fmaxf(vb.w + sb1[cb + 7], 0.f));
                asm volatile(
                    "red.global.add.noftz.v4.f16x2 [%0], {%1,%2,%3,%4};" ::
                    "l"(dst + q * 8), "r"(p0), "r"(p1), "r"(p2), "r"(p3)
                    : "memory");
            }
        }
    }
}

// ---------------- GEMM2 (HMMA fp16): out = relu(aggh)@W2 + b2 ----------------
// CTA: M=128, N=40 (5 n8 tiles exactly), K=256. Warp tile 16x40.
#define G2_SMEM 88704    // A(67584)+B(21120)

__global__ __launch_bounds__(256, 2)
void k_g2(const float* __restrict__ b2, float* __restrict__ out) {
    extern __shared__ __align__(16) char sm[];
    __shared__ float sb2[CC];
    uint32_t sA = smem_u32(sm);
    uint32_t sB = sA + 67584;

    int tid = threadIdx.x, lane = tid & 31, wid = tid >> 5;
    int rowBase = blockIdx.x * 128;
    int U = g_U;

    if (tid < CC) sb2[tid] = b2[tid];

    // early-out: entire tile beyond live segments -> out = b2
    if (rowBase >= U) {
        __syncthreads();
#pragma unroll
        for (int q = tid; q < 128 * CC; q += 256) {
            int r = q / CC, c = q - r * CC;
            int grow = rowBase + r;
            if (grow < NN) out[(size_t)grow * CC + c] = sb2[c];
        }
        return;
    }

    {
        const uint4* srcH = (const uint4*)g_B2h;
        uint4* dH = (uint4*)(sm + 67584);
#pragma unroll
        for (int i = tid; i < 1320; i += 256) dH[i] = srcH[i];
    }
    // stage A = relu(aggh) directly in fp16; rows >= U are zeros; pitch 528B
    {
        const __half2 z2 = __float2half2_rn(0.f);
#pragma unroll
        for (int q = tid; q < 4096; q += 256) {
            int m = q >> 5, g = q & 31;      // 8 halves per step
            int row = rowBase + m;
            uint4 v = make_uint4(0, 0, 0, 0);
            if (row < U) {
                v = __ldcs((const uint4*)&g_aggh[(size_t)row * HH + g * 8]);
                __half2* h = (__half2*)&v;
#pragma unroll
                for (int e = 0; e < 4; e++) h[e] = __hmax2(h[e], z2);
            }
            *(uint4*)(sm + m * 528 + g * 16) = v;
        }
    }
    __syncthreads();

    int m0 = wid * 16;
    float acc[5][4];
#pragma unroll
    for (int j = 0; j < 5; j++)
#pragma unroll
        for (int e = 0; e < 4; e++) acc[j][e] = 0.f;

#pragma unroll
    for (int ks = 0; ks < 16; ks++) {
        uint32_t af[4];
        uint32_t ad = sA + (m0 + (lane & 15)) * 528 +
                      (ks * 16 + (lane >> 4) * 8) * 2;
        LDSM4(af, ad);
        uint32_t bf[5][2];
#pragma unroll
        for (int pq = 0; pq < 2; pq++) {
            uint32_t r4[4];
            uint32_t bd = sB +
                (pq * 16 + ((lane >> 4) & 1) * 8 + (lane & 7)) * 528 +
                (ks * 16 + ((lane >> 3) & 1) * 8) * 2;
            LDSM4(r4, bd);
            bf[2 * pq][0] = r4[0]; bf[2 * pq][1] = r4[1];
            bf[2 * pq + 1][0] = r4[2]; bf[2 * pq + 1][1] = r4[3];
        }
        {
            uint32_t bd2 = sB + (32 + (lane & 7)) * 528 +
                           (ks * 16 + ((lane >> 3) & 1) * 8) * 2;
            LDSM2(bf[4], bd2);
        }
#pragma unroll
        for (int nt = 0; nt < 5; nt++) MMA16816(acc[nt], af, bf[nt]);
    }

    // epilogue: direct stores with bias
    int r0 = m0 + (lane >> 2);
#pragma unroll
    for (int nt = 0; nt < 5; nt++) {
        int col = nt * 8 + (lane & 3) * 2;
        float bx = sb2[col], by = sb2[col + 1];
        int gA = rowBase + r0, gB = gA + 8;
        if (gA < NN)
            *(float2*)&out[(size_t)gA * CC + col] =
                make_float2(acc[nt][0] + bx, acc[nt][1] + by);
        if (gB < NN)
            *(float2*)&out[(size_t)gB * CC + col] =
                make_float2(acc[nt][2] + bx, acc[nt][3] + by);
    }
}

// ---------------- launch ----------------
extern "C" void kernel_launch(void* const* d_in, const int* in_sizes, int n_in,
                              void* d_out, int out_size) {
    const float* x  = (const float*)d_in[0];
    const int*   ei = (const int*)d_in[1];
    const float* W1 = (const float*)d_in[2];
    const float* b1 = (const float*)d_in[3];
    const float* W2 = (const float*)d_in[4];
    const float* b2 = (const float*)d_in[5];
    float* out = (float*)d_out;

    cudaFuncSetAttribute(k_g1, cudaFuncAttributeMaxDynamicSharedMemorySize,
                         G1_SMEM);
    cudaFuncSetAttribute(k_g2, cudaFuncAttributeMaxDynamicSharedMemorySize,
                         G2_SMEM);

    int nb = (NN + 255) / 256;
    k_init_firstpos<<<nb, 256>>>();
    k_firstpos<<<nb, 256>>>(ei);
    k_scan1<<<NBLK, 256>>>(ei);
    k_scan2<<<1, 256>>>();
    k_mapped<<<nb, 256>>>(ei);
    // partition rows by target half (reuses scan scratch)
    k_scanA1<<<NBLK, 256>>>();
    k_scanA2<<<1, 256>>>();
    k_fill<<<nb, 256>>>();
    k_prep1<<<(HH * FF + 255) / 256, 256>>>(W1);
    k_prep2<<<(CC * HH + 255) / 256, 256>>>(W2);

    int rowTiles = (NN + 127) / 128;   // 3907 (upper bound per pass)
    k_zero_rows<<<2048, 256>>>(0);
    k_g1<<<rowTiles, 512, G1_SMEM>>>(x, b1, 0);
    k_zero_rows<<<2048, 256>>>(1);
    k_g1<<<rowTiles, 512, G1_SMEM>>>(x, b1, 1);

    k_g2<<<rowTiles, 256, G2_SMEM>>>(b2, out);
}

// round 16
// speedup vs baseline: 1.2088x; 1.2088x over previous
#include <cuda_runtime.h>
#include <cuda_fp16.h>
#include <cstdint>

#define NN 500000
#define FF 128
#define HH 256
#define CC 40
#define IPB 2048                       // items per scan block (256 thr x 8)
#define NBLK ((NN + IPB - 1) / IPB)    // 245

static_assert(NBLK <= 256, "scan2 single block");

// ---- scratch (device globals; no allocations allowed) ----
__device__ int g_first_pos[NN];
__device__ int g_excl[NN];
__device__ int g_bsum[NBLK];
__device__ int g_bsumx[NBLK];
__device__ int g_mapped[NN];
__device__ int g_U;
__device__ __align__(128) __half g_aggh[(size_t)NN * HH];   // 256 MB fp16

// pre-converted fp16 W images, transposed to [n][k] with ldmatrix pitch
// pitch1 = 272 B (272 % 128 == 16 -> conflict-free ldmatrix)
// pitch2 = 528 B (528 % 128 == 16)
__device__ __align__(16) unsigned char g_B1h[256 * 272];
__device__ __align__(16) unsigned char g_B2h[40 * 528];

// ---------------- helpers ----------------

__device__ __forceinline__ uint32_t smem_u32(const void* p) {
    uint32_t a;
    asm("{ .reg .u64 t; cvta.to.shared.u64 t, %1; cvt.u32.u64 %0, t; }"
        : "=r"(a) : "l"(p));
    return a;
}

__device__ __forceinline__ uint32_t f2h2u(float a, float b) {
    __half2 h = __floats2half2_rn(a, b);
    return *reinterpret_cast<uint32_t*>(&h);
}

#define LDSM4(r, addr)                                                         \
    asm volatile("ldmatrix.sync.aligned.m8n8.x4.shared.b16 {%0,%1,%2,%3},[%4];"\
                 : "=r"((r)[0]), "=r"((r)[1]), "=r"((r)[2]), "=r"((r)[3])      \
                 : "r"(addr))
#define LDSM2(r, addr)                                                         \
    asm volatile("ldmatrix.sync.aligned.m8n8.x2.shared.b16 {%0,%1},[%2];"      \
                 : "=r"((r)[0]), "=r"((r)[1]) : "r"(addr))
#define MMA16816(d, a, b)                                                      \
    asm volatile(                                                              \
        "mma.sync.aligned.m16n8k16.row.col.f32.f16.f16.f32 "                   \
        "{%0,%1,%2,%3},{%4,%5,%6,%7},{%8,%9},{%0,%1,%2,%3};"                   \
        : "+f"((d)[0]), "+f"((d)[1]), "+f"((d)[2]), "+f"((d)[3])               \
        : "r"((a)[0]), "r"((a)[1]), "r"((a)[2]), "r"((a)[3]),                  \
          "r"((b)[0]), "r"((b)[1]))

// ---------------- fused setup: init_firstpos + prep1 + prep2 ----------------
// blocks [0, NB_INIT): first_pos init
// blocks [NB_INIT, NB_INIT+128): W1 prep (32768 elems)
// blocks [NB_INIT+128, NB_INIT+168): W2 prep (10240 elems)
#define NB_INIT ((NN + 255) / 256)     // 1954

__global__ void k_setup(const float* __restrict__ W1,
                        const float* __restrict__ W2) {
    int b = blockIdx.x, t = threadIdx.x;
    if (b < NB_INIT) {
        int i = b * 256 + t;
        if (i < NN) g_first_pos[i] = NN;
    } else if (b < NB_INIT + 128) {
        int idx = (b - NB_INIT) * 256 + t;          // < 32768 = HH*FF
        int n = idx >> 7, k = idx & 127;
        float v = W1[(size_t)k * HH + n];
        uint32_t off = (uint32_t)n * 272 + (uint32_t)k * 2;
        *(unsigned short*)(g_B1h + off) = __half_as_ushort(__float2half_rn(v));
    } else {
        int idx = (b - NB_INIT - 128) * 256 + t;    // < 10240 = CC*HH
        if (idx < CC * HH) {
            int n = idx >> 8, k = idx & 255;
            float v = W2[(size_t)k * CC + n];
            uint32_t off = (uint32_t)n * 528 + (uint32_t)k * 2;
            *(unsigned short*)(g_B2h + off) =
                __half_as_ushort(__float2half_rn(v));
        }
    }
}

__global__ void k_firstpos(const int* __restrict__ ei) {
    int i = blockIdx.x * blockDim.x + threadIdx.x;
    if (i < NN) atomicMin(&g_first_pos[ei[2 * i]], i);
}

__global__ __launch_bounds__(256) void k_scan1(const int* __restrict__ ei) {
    int t = threadIdx.x, b = blockIdx.x;
    int base = b * IPB + t * 8;
    int f[8]; int ls = 0;
#pragma unroll
    for (int j = 0; j < 8; j++) {
        int i = base + j;
        int v = 0;
        if (i < NN) { int s = ei[2 * i]; v = (g_first_pos[s] == i) ? 1 : 0; }
        f[j] = v; ls += v;
    }
    int lane = t & 31, wid = t >> 5;
    int incl = ls;
#pragma unroll
    for (int o = 1; o < 32; o <<= 1) {
        int n = __shfl_up_sync(0xffffffffu, incl, o);
        if (lane >= o) incl += n;
    }
    __shared__ int wtot[8], woff[8];
    if (lane == 31) wtot[wid] = incl;
    __syncthreads();
    if (t < 8) {
        int s = 0;
        for (int j = 0; j < t; j++) s += wtot[j];
        woff[t] = s;
    }
    __syncthreads();
    int run = woff[wid] + (incl - ls);
#pragma unroll
    for (int j = 0; j < 8; j++) {
        int i = base + j;
        if (i < NN) g_excl[i] = run;
        run += f[j];
    }
    if (t == 255) g_bsum[b] = run;
}

__global__ __launch_bounds__(256) void k_scan2() {
    int t = threadIdx.x;
    int v = (t < NBLK) ? g_bsum[t] : 0;
    int lane = t & 31, wid = t >> 5;
    int incl = v;
#pragma unroll
    for (int o = 1; o < 32; o <<= 1) {
        int n = __shfl_up_sync(0xffffffffu, incl, o);
        if (lane >= o) incl += n;
    }
    __shared__ int wtot[8], woff[8];
    if (lane == 31) wtot[wid] = incl;
    __syncthreads();
    if (t < 8) {
        int s = 0;
        for (int j = 0; j < t; j++) s += wtot[j];
        woff[t] = s;
    }
    __syncthreads();
    int excl = woff[wid] + incl - v;
    if (t < NBLK) g_bsumx[t] = excl;
    if (t == 255) g_U = excl + v;
}

// fused: mapped (blocks [0, NB_INIT)) + zero agg col-half 0 (remaining blocks)
#define NB_ZERO 2048

__global__ void k_mapped_zero0(const int* __restrict__ ei) {
    int b = blockIdx.x, t = threadIdx.x;
    if (b < NB_INIT) {
        int i = b * 256 + t;
        if (i < NN) {
            int j  = ei[2 * i];
            int s2 = ei[2 * j];
            int p  = g_first_pos[s2];
            g_mapped[i] = g_excl[p] + g_bsumx[p / IPB];
        }
    } else {
        int U = g_U;
        size_t total = (size_t)U * 16;         // 16 uint4 per row col-half
        uint4* p = (uint4*)g_aggh;
        uint4 z = make_uint4(0, 0, 0, 0);
        for (size_t i = (size_t)(b - NB_INIT) * 256 + t; i < total;
             i += (size_t)NB_ZERO * 256) {
            size_t row = i >> 4;
            int c = (int)(i & 15);
            p[row * 32 + c] = z;
        }
    }
}

// zero col-half 1 of agg for live rows [0, U)
__global__ void k_zero_half1() {
    int U = g_U;
    size_t total = (size_t)U * 16;
    uint4* p = (uint4*)g_aggh;
    uint4 z = make_uint4(0, 0, 0, 0);
    for (size_t i = blockIdx.x * (size_t)blockDim.x + threadIdx.x; i < total;
         i += (size_t)gridDim.x * blockDim.x) {
        size_t row = i >> 4;
        int c = (int)(i & 15);
        p[row * 32 + 16 + c] = z;
    }
}

// ---------------- GEMM1 (HMMA fp16): relu(x@W1+b1) fused scatter ----------------
// CTA: M=128 rows, N=128 cols, K=128. colTile passed as arg. Warp tile 32x64.
#define G1_SMEM 69632    // A(34816)+B(34816); Cs(67584) reuses it

__global__ __launch_bounds__(256, 2)
void k_g1(const float* __restrict__ x, const float* __restrict__ b1,
          int colTile) {
    extern __shared__ __align__(16) char sm[];
    __shared__ float sb1[128];
    uint32_t sA = smem_u32(sm);
    uint32_t sB = sA + 34816;

    int tid = threadIdx.x, lane = tid & 31, wid = tid >> 5;
    int rowBase = blockIdx.x * 128, colBase = colTile * 128;

    if (tid < 128) sb1[tid] = b1[colBase + tid];

    // copy pre-converted B slice (rows colBase..colBase+127), pitch 272B
    {
        const uint4* srcH = (const uint4*)(g_B1h + (size_t)colBase * 272);
        uint4* dH = (uint4*)(sm + 34816);
#pragma unroll
        for (int i = tid; i < 2176; i += 256) dH[i] = srcH[i];
    }
    // stage A: convert x rows to fp16, pitch 272B (streaming x loads)
#pragma unroll
    for (int q = tid; q < 2048; q += 256) {
        int m = q >> 4, g = q & 15;
        int row = rowBase + m;
        float a[8];
        if (row < NN) {
            float4 v0 = __ldcs((const float4*)&x[(size_t)row * FF + g * 8]);
            float4 v1 = __ldcs((const float4*)&x[(size_t)row * FF + g * 8 + 4]);
            a[0] = v0.x; a[1] = v0.y; a[2] = v0.z; a[3] = v0.w;
            a[4] = v1.x; a[5] = v1.y; a[6] = v1.z; a[7] = v1.w;
        } else {
#pragma unroll
            for (int j = 0; j < 8; j++) a[j] = 0.f;
        }
        uint4 ph;
        ph.x = f2h2u(a[0], a[1]);
        ph.y = f2h2u(a[2], a[3]);
        ph.z = f2h2u(a[4], a[5]);
        ph.w = f2h2u(a[6], a[7]);
        *(uint4*)(sm + m * 272 + g * 16) = ph;
    }
    __syncthreads();

    int mRow = (wid & 3) * 32, nCol = (wid >> 2) * 64;
    float acc[2][8][4];
#pragma unroll
    for (int i = 0; i < 2; i++)
#pragma unroll
        for (int j = 0; j < 8; j++)
#pragma unroll
            for (int e = 0; e < 4; e++) acc[i][j][e] = 0.f;

#pragma unroll
    for (int ks = 0; ks < 8; ks++) {
        uint32_t af[2][4];
#pragma unroll
        for (int mt = 0; mt < 2; mt++) {
            uint32_t ad = sA + (mRow + mt * 16 + (lane & 15)) * 272 +
                          (ks * 16 + (lane >> 4) * 8) * 2;
            LDSM4(af[mt], ad);
        }
        uint32_t bf[8][2];
#pragma unroll
        for (int p = 0; p < 4; p++) {
            uint32_t r4[4];
            uint32_t bd = sB +
                (nCol + p * 16 + ((lane >> 4) & 1) * 8 + (lane & 7)) * 272 +
                (ks * 16 + ((lane >> 3) & 1) * 8) * 2;
            LDSM4(r4, bd);
            bf[2 * p][0] = r4[0]; bf[2 * p][1] = r4[1];
            bf[2 * p + 1][0] = r4[2]; bf[2 * p + 1][1] = r4[3];
        }
#pragma unroll
        for (int mt = 0; mt < 2; mt++)
#pragma unroll
            for (int nt = 0; nt < 8; nt++)
                MMA16816(acc[mt][nt], af[mt], bf[nt]);
    }
    __syncthreads();   // before overwriting A/B region with Cs

    // stage acc to smem (Cs: 128 rows x pitch 132 floats, fits in A+B)
    float* Cs = (float*)sm;
#pragma unroll
    for (int mt = 0; mt < 2; mt++)
#pragma unroll
        for (int nt = 0; nt < 8; nt++) {
            int r = mRow + mt * 16 + (lane >> 2);
            int cc = nCol + nt * 8 + (lane & 3) * 2;
            *(float2*)&Cs[r * 132 + cc] =
                make_float2(acc[mt][nt][0], acc[mt][nt][1]);
            *(float2*)&Cs[(r + 8) * 132 + cc] =
                make_float2(acc[mt][nt][2], acc[mt][nt][3]);
        }
    __syncthreads();

    // scatter: bias + relu + red.global.add.v4.f16x2 into aggh[mapped[row]]
    int row = tid & 127, half = tid >> 7;
    int grow = rowBase + row;
    if (grow < NN) {
        int tgt = g_mapped[grow];
        __half* dst = g_aggh + (size_t)tgt * HH + colBase + half * 64;
        const float* csrc = Cs + row * 132 + half * 64;
#pragma unroll
        for (int q = 0; q < 8; q++) {
            float4 va = *(const float4*)&csrc[q * 8];
            float4 vb = *(const float4*)&csrc[q * 8 + 4];
            int cb = half * 64 + q * 8;
            uint32_t p0 = f2h2u(fmaxf(va.x + sb1[cb], 0.f),
                                fmaxf(va.y + sb1[cb + 1], 0.f));
            uint32_t p1 = f2h2u(fmaxf(va.z + sb1[cb + 2], 0.f),
                                fmaxf(va.w + sb1[cb + 3], 0.f));
            uint32_t p2 = f2h2u(fmaxf(vb.x + sb1[cb + 4], 0.f),
                                fmaxf(vb.y + sb1[cb + 5], 0.f));
            uint32_t p3 = f2h2u(fmaxf(vb.z + sb1[cb + 6], 0.f),
                                fmaxf(vb.w + sb1[cb + 7], 0.f));
            asm volatile(
                "red.global.add.noftz.v4.f16x2 [%0], {%1,%2,%3,%4};" ::
                "l"(dst + q * 8), "r"(p0), "r"(p1), "r"(p2), "r"(p3)
                : "memory");
        }
    }
}

// ---------------- GEMM2 (HMMA fp16): out = relu(aggh)@W2 + b2 ----------------
// CTA: M=128, N=40 (5 n8 tiles exactly), K=256. Warp tile 16x40.
#define G2_SMEM 88704    // A(67584)+B(21120)

__global__ __launch_bounds__(256, 2)
void k_g2(const float* __restrict__ b2, float* __restrict__ out) {
    extern __shared__ __align__(16) char sm[];
    __shared__ float sb2[CC];
    uint32_t sA = smem_u32(sm);
    uint32_t sB = sA + 67584;

    int tid = threadIdx.x, lane = tid & 31, wid = tid >> 5;
    int rowBase = blockIdx.x * 128;
    int U = g_U;

    if (tid < CC) sb2[tid] = b2[tid];

    // early-out: entire tile beyond live segments -> out = b2
    if (rowBase >= U) {
        __syncthreads();
#pragma unroll
        for (int q = tid; q < 128 * CC; q += 256) {
            int r = q / CC, c = q - r * CC;
            int grow = rowBase + r;
            if (grow < NN) out[(size_t)grow * CC + c] = sb2[c];
        }
        return;
    }

    {
        const uint4* srcH = (const uint4*)g_B2h;
        uint4* dH = (uint4*)(sm + 67584);
#pragma unroll
        for (int i = tid; i < 1320; i += 256) dH[i] = srcH[i];
    }
    // stage A = relu(aggh) directly in fp16; rows >= U are zeros; pitch 528B
    {
        const __half2 z2 = __float2half2_rn(0.f);
#pragma unroll
        for (int q = tid; q < 4096; q += 256) {
            int m = q >> 5, g = q & 31;      // 8 halves per step
            int row = rowBase + m;
            uint4 v = make_uint4(0, 0, 0, 0);
            if (row < U) {
                v = __ldcs((const uint4*)&g_aggh[(size_t)row * HH + g * 8]);
                __half2* h = (__half2*)&v;
#pragma unroll
                for (int e = 0; e < 4; e++) h[e] = __hmax2(h[e], z2);
            }
            *(uint4*)(sm + m * 528 + g * 16) = v;
        }
    }
    __syncthreads();

    int m0 = wid * 16;
    float acc[5][4];
#pragma unroll
    for (int j = 0; j < 5; j++)
#pragma unroll
        for (int e = 0; e < 4; e++) acc[j][e] = 0.f;

#pragma unroll
    for (int ks = 0; ks < 16; ks++) {
        uint32_t af[4];
        uint32_t ad = sA + (m0 + (lane & 15)) * 528 +
                      (ks * 16 + (lane >> 4) * 8) * 2;
        LDSM4(af, ad);
        uint32_t bf[5][2];
#pragma unroll
        for (int p = 0; p < 2; p++) {
            uint32_t r4[4];
            uint32_t bd = sB +
                (p * 16 + ((lane >> 4) & 1) * 8 + (lane & 7)) * 528 +
                (ks * 16 + ((lane >> 3) & 1) * 8) * 2;
            LDSM4(r4, bd);
            bf[2 * p][0] = r4[0]; bf[2 * p][1] = r4[1];
            bf[2 * p + 1][0] = r4[2]; bf[2 * p + 1][1] = r4[3];
        }
        {
            uint32_t bd2 = sB + (32 + (lane & 7)) * 528 +
                           (ks * 16 + ((lane >> 3) & 1) * 8) * 2;
            LDSM2(bf[4], bd2);
        }
#pragma unroll
        for (int nt = 0; nt < 5; nt++) MMA16816(acc[nt], af, bf[nt]);
    }

    // epilogue: direct stores with bias
    int r0 = m0 + (lane >> 2);
#pragma unroll
    for (int nt = 0; nt < 5; nt++) {
        int col = nt * 8 + (lane & 3) * 2;
        float bx = sb2[col], by = sb2[col + 1];
        int gA = rowBase + r0, gB = gA + 8;
        if (gA < NN)
            *(float2*)&out[(size_t)gA * CC + col] =
                make_float2(acc[nt][0] + bx, acc[nt][1] + by);
        if (gB < NN)
            *(float2*)&out[(size_t)gB * CC + col] =
                make_float2(acc[nt][2] + bx, acc[nt][3] + by);
    }
}

// ---------------- launch ----------------
extern "C" void kernel_launch(void* const* d_in, const int* in_sizes, int n_in,
                              void* d_out, int out_size) {
    const float* x  = (const float*)d_in[0];
    const int*   ei = (const int*)d_in[1];
    const float* W1 = (const float*)d_in[2];
    const float* b1 = (const float*)d_in[3];
    const float* W2 = (const float*)d_in[4];
    const float* b2 = (const float*)d_in[5];
    float* out = (float*)d_out;

    cudaFuncSetAttribute(k_g1, cudaFuncAttributeMaxDynamicSharedMemorySize,
                         G1_SMEM);
    cudaFuncSetAttribute(k_g2, cudaFuncAttributeMaxDynamicSharedMemorySize,
                         G2_SMEM);

    k_setup<<<NB_INIT + 128 + 40, 256>>>(W1, W2);
    k_firstpos<<<NB_INIT, 256>>>(ei);
    k_scan1<<<NBLK, 256>>>(ei);
    k_scan2<<<1, 256>>>();
    k_mapped_zero0<<<NB_INIT + NB_ZERO, 256>>>(ei);

    int rowTiles = (NN + 127) / 128;   // 3907
    k_g1<<<rowTiles, 256, G1_SMEM>>>(x, b1, 0);
    k_zero_half1<<<NB_ZERO, 256>>>();
    k_g1<<<rowTiles, 256, G1_SMEM>>>(x, b1, 1);

    k_g2<<<rowTiles, 256, G2_SMEM>>>(b2, out);
}